// round 1
// baseline (speedup 1.0000x reference)
#include <cuda_runtime.h>
#include <cstdint>

#define N_NODES 100000
#define E_EDGES 1600000
#define IN_DIM  256
#define HCOLS   256   // 2 graphs * 128 h-cols

// ---------------- scratch (device globals; no runtime allocation) ----------------
static __device__ float4 g_h4  [N_NODES * 64];   // h for both graphs: [n][256] floats
static __device__ float4 g_acc4[N_NODES * 64];   // aggregated messages, same layout
static __device__ float  g_asrc[N_NODES * 4];    // [n][graph*2+head]
static __device__ float  g_adst[N_NODES * 4];
static __device__ float  g_m   [N_NODES * 4];    // segment max
static __device__ float  g_den [N_NODES * 4];    // segment sum of exp

__device__ __forceinline__ float lrelu(float x) { return x >= 0.f ? x : 0.2f * x; }

__device__ __forceinline__ void atomicMaxF(float* a, float v) {
    unsigned u = __float_as_uint(v);
    if (u & 0x80000000u) {
        if (u == 0x80000000u) atomicMax((int*)a, 0);          // -0 -> +0
        else atomicMin((unsigned int*)a, u);                  // negative: smaller unsigned = larger float? no: larger unsigned = more negative -> min keeps max
    } else {
        atomicMax((int*)a, (int)u);
    }
}

// ---------------- init: zero acc & den, -inf max ----------------
__global__ void k_init() {
    int i = blockIdx.x * blockDim.x + threadIdx.x;
    if (i < N_NODES * 64) g_acc4[i] = make_float4(0.f, 0.f, 0.f, 0.f);
    if (i < N_NODES * 4) {
        g_m[i]   = __int_as_float(0xff800000);  // -inf
        g_den[i] = 0.f;
    }
}

// ---------------- GEMM: h[n][0:128]=x@W1, h[n][128:256]=x@W2 ----------------
// BM=64, BN=64, BK=16, 256 threads, 4x4 per thread
__global__ void k_gemm(const float* __restrict__ x,
                       const float* __restrict__ W1,
                       const float* __restrict__ W2) {
    __shared__ float As[16][64];
    __shared__ float Bs[16][64];

    const int cb = blockIdx.y;                 // 0..3 (col block of 64)
    const float* W = (cb < 2) ? W1 : W2;
    const int colbase = (cb & 1) * 64;         // within the 128-col W
    const int n0 = blockIdx.x * 64;
    const int t  = threadIdx.x;
    const int tx = t & 15, ty = t >> 4;

    // load indexing
    const int lr = t >> 2;            // x-tile row 0..63
    const int lk = (t & 3) * 4;       // x-tile k offset
    const int wk = t >> 4;            // W-tile k row 0..15
    const int wc = (t & 15) * 4;      // W-tile col offset

    float acc[4][4];
#pragma unroll
    for (int i = 0; i < 4; i++)
#pragma unroll
        for (int j = 0; j < 4; j++) acc[i][j] = 0.f;

    for (int k0 = 0; k0 < IN_DIM; k0 += 16) {
        float4 xv = make_float4(0.f, 0.f, 0.f, 0.f);
        int n = n0 + lr;
        if (n < N_NODES) xv = *(const float4*)(x + (size_t)n * IN_DIM + k0 + lk);
        As[lk + 0][lr] = xv.x;
        As[lk + 1][lr] = xv.y;
        As[lk + 2][lr] = xv.z;
        As[lk + 3][lr] = xv.w;

        float4 wv = *(const float4*)(W + (size_t)(k0 + wk) * 128 + colbase + wc);
        *(float4*)&Bs[wk][wc] = wv;
        __syncthreads();

#pragma unroll
        for (int kk = 0; kk < 16; kk++) {
            float4 av = *(const float4*)&As[kk][ty * 4];
            float4 bv = *(const float4*)&Bs[kk][tx * 4];
            float a[4] = {av.x, av.y, av.z, av.w};
            float b[4] = {bv.x, bv.y, bv.z, bv.w};
#pragma unroll
            for (int i = 0; i < 4; i++)
#pragma unroll
                for (int j = 0; j < 4; j++) acc[i][j] = fmaf(a[i], b[j], acc[i][j]);
        }
        __syncthreads();
    }

    const int gcol = cb * 64 + tx * 4;   // global h column 0..255
    float* hout = (float*)g_h4;
#pragma unroll
    for (int i = 0; i < 4; i++) {
        int n = n0 + ty * 4 + i;
        if (n < N_NODES) {
            float4 st = make_float4(acc[i][0], acc[i][1], acc[i][2], acc[i][3]);
            *(float4*)(hout + (size_t)n * HCOLS + gcol) = st;
        }
    }
}

// ---------------- per-node attention dot products ----------------
__global__ void k_dots(const float* __restrict__ as1, const float* __restrict__ ad1,
                       const float* __restrict__ as2, const float* __restrict__ ad2) {
    const int n = blockIdx.x;
    const int t = threadIdx.x;               // 256
    const int graph = t >> 7;
    const int head  = (t >> 6) & 1;
    const int ch    = t & 63;
    const float* As = graph ? as2 : as1;
    const float* Ad = graph ? ad2 : ad1;

    float h = ((const float*)g_h4)[(size_t)n * HCOLS + t];
    float vs = h * As[head * 64 + ch];
    float vd = h * Ad[head * 64 + ch];

    __shared__ float ss[256], sd[256];
    ss[t] = vs; sd[t] = vd;
    __syncthreads();
    if ((t & 63) < 32) {
        vs = ss[t] + ss[t + 32];
        vd = sd[t] + sd[t + 32];
#pragma unroll
        for (int off = 16; off; off >>= 1) {
            vs += __shfl_down_sync(0xffffffffu, vs, off);
            vd += __shfl_down_sync(0xffffffffu, vd, off);
        }
        if ((t & 63) == 0) {
            int gi = t >> 6;                 // graph*2 + head
            g_asrc[(size_t)n * 4 + gi] = vs;
            g_adst[(size_t)n * 4 + gi] = vd;
        }
    }
}

// ---------------- edge pass 1: segment max ----------------
__global__ void k_max(const int* __restrict__ eic, const int* __restrict__ eil, int EN) {
    int idx = blockIdx.x * blockDim.x + threadIdx.x;
    if (idx >= EN) return;
    int g = blockIdx.y;
    const int* ei = g ? eil : eic;
    int src, dst;
    if (idx < E_EDGES) { src = ei[idx]; dst = ei[E_EDGES + idx]; }
    else               { src = dst = idx - E_EDGES; }
    int bs = src * 4 + g * 2, bd = dst * 4 + g * 2;
    float e0 = lrelu(g_asrc[bs]     + g_adst[bd]);
    float e1 = lrelu(g_asrc[bs + 1] + g_adst[bd + 1]);
    atomicMaxF(&g_m[bd],     e0);
    atomicMaxF(&g_m[bd + 1], e1);
}

// ---------------- edge pass 2: denom = sum exp(e - m) ----------------
__global__ void k_den(const int* __restrict__ eic, const int* __restrict__ eil, int EN) {
    int idx = blockIdx.x * blockDim.x + threadIdx.x;
    if (idx >= EN) return;
    int g = blockIdx.y;
    const int* ei = g ? eil : eic;
    int src, dst;
    if (idx < E_EDGES) { src = ei[idx]; dst = ei[E_EDGES + idx]; }
    else               { src = dst = idx - E_EDGES; }
    int bs = src * 4 + g * 2, bd = dst * 4 + g * 2;
    float e0 = lrelu(g_asrc[bs]     + g_adst[bd]);
    float e1 = lrelu(g_asrc[bs + 1] + g_adst[bd + 1]);
    atomicAdd(&g_den[bd],     __expf(e0 - g_m[bd]));
    atomicAdd(&g_den[bd + 1], __expf(e1 - g_m[bd + 1]));
}

// ---------------- edge pass 3: scatter messages (1 warp / edge) ----------------
__global__ void k_scatter(const int* __restrict__ eic, const int* __restrict__ eil, int EN) {
    int gt = blockIdx.x * blockDim.x + threadIdx.x;
    int w = gt >> 5, lane = gt & 31;
    if (w >= EN) return;
    int g = blockIdx.y;
    const int* ei = g ? eil : eic;
    int src, dst;
    if (w < E_EDGES) { src = ei[w]; dst = ei[E_EDGES + w]; }
    else             { src = dst = w - E_EDGES; }

    float alpha0 = 0.f, alpha1 = 0.f;
    if (lane == 0) {
        int bs = src * 4 + g * 2, bd = dst * 4 + g * 2;
        float e0 = lrelu(g_asrc[bs]     + g_adst[bd]);
        float e1 = lrelu(g_asrc[bs + 1] + g_adst[bd + 1]);
        alpha0 = __expf(e0 - g_m[bd])     / g_den[bd];
        alpha1 = __expf(e1 - g_m[bd + 1]) / g_den[bd + 1];
    }
    alpha0 = __shfl_sync(0xffffffffu, alpha0, 0);
    alpha1 = __shfl_sync(0xffffffffu, alpha1, 0);
    float alpha = (lane < 16) ? alpha0 : alpha1;   // head = lane/16

    float4 v = g_h4[(size_t)src * 64 + g * 32 + lane];
    v.x *= alpha; v.y *= alpha; v.z *= alpha; v.w *= alpha;
    float4* dp = &g_acc4[(size_t)dst * 64 + g * 32 + lane];
    asm volatile("red.global.add.v4.f32 [%0], {%1,%2,%3,%4};"
                 :: "l"(dp), "f"(v.x), "f"(v.y), "f"(v.z), "f"(v.w) : "memory");
}

// ---------------- fused bias+relu+concat+FC ----------------
// 256 threads: 16 nodes/block, each thread does (node = t/16, 4 outputs at (t%16)*4)
__global__ void k_fc(const float* __restrict__ b1, const float* __restrict__ b2,
                     const float* __restrict__ fcW, const float* __restrict__ fcb,
                     float* __restrict__ out) {
    __shared__ float s[16][256];
    const int n0 = blockIdx.x * 16;
    const int t  = threadIdx.x;

#pragma unroll
    for (int i = 0; i < 16; i++) {
        int k = t;                       // 0..255
        float b = (k < 128) ? b1[k] : b2[k - 128];
        float v = ((const float*)g_acc4)[(size_t)(n0 + i) * HCOLS + k] + b;
        s[i][k] = fmaxf(v, 0.f);
    }
    __syncthreads();

    const int node = t >> 4;
    const int o4   = (t & 15) * 4;
    float acc[4];
    float4 bb = *(const float4*)(fcb + o4);
    acc[0] = bb.x; acc[1] = bb.y; acc[2] = bb.z; acc[3] = bb.w;
#pragma unroll 8
    for (int k = 0; k < 256; k++) {
        float sv = s[node][k];
        float4 wv = *(const float4*)(fcW + (size_t)k * 64 + o4);
        acc[0] = fmaf(sv, wv.x, acc[0]);
        acc[1] = fmaf(sv, wv.y, acc[1]);
        acc[2] = fmaf(sv, wv.z, acc[2]);
        acc[3] = fmaf(sv, wv.w, acc[3]);
    }
    float4 st = make_float4(acc[0], acc[1], acc[2], acc[3]);
    *(float4*)(out + (size_t)(n0 + node) * 64 + o4) = st;
}

// ---------------- launcher ----------------
extern "C" void kernel_launch(void* const* d_in, const int* in_sizes, int n_in,
                              void* d_out, int out_size) {
    const float* x   = (const float*)d_in[0];
    const int*   eic = (const int*)d_in[1];
    const int*   eil = (const int*)d_in[2];
    const float* W1  = (const float*)d_in[3];
    const float* as1 = (const float*)d_in[4];
    const float* ad1 = (const float*)d_in[5];
    const float* b1  = (const float*)d_in[6];
    const float* W2  = (const float*)d_in[7];
    const float* as2 = (const float*)d_in[8];
    const float* ad2 = (const float*)d_in[9];
    const float* b2  = (const float*)d_in[10];
    const float* fcW = (const float*)d_in[11];
    const float* fcb = (const float*)d_in[12];
    float* out = (float*)d_out;

    const int EN = E_EDGES + N_NODES;

    k_init<<<(N_NODES * 64 + 255) / 256, 256>>>();

    dim3 gg((N_NODES + 63) / 64, 4);
    k_gemm<<<gg, 256>>>(x, W1, W2);

    k_dots<<<N_NODES, 256>>>(as1, ad1, as2, ad2);

    dim3 ge((EN + 255) / 256, 2);
    k_max<<<ge, 256>>>(eic, eil, EN);
    k_den<<<ge, 256>>>(eic, eil, EN);

    dim3 gs((EN + 7) / 8, 2);   // 1 warp per edge, 8 warps per block
    k_scatter<<<gs, 256>>>(eic, eil, EN);

    k_fc<<<N_NODES / 16, 256>>>(b1, b2, fcW, fcb, out);
}

// round 2
// speedup vs baseline: 1.1133x; 1.1133x over previous
#include <cuda_runtime.h>
#include <cstdint>

#define N_NODES 100000
#define E_EDGES 1600000
#define NSEG    (2*N_NODES)
#define EN_TOT  (E_EDGES + N_NODES)

typedef unsigned long long ull;

// ---------------- device scratch (no runtime allocation) ----------------
static __device__ float4 g_h4  [N_NODES * 64];   // h both graphs: [n][256] floats
static __device__ float4 g_acc4[N_NODES * 64];   // relu(agg + bias), same layout
static __device__ float  g_asrc[N_NODES * 4];    // [n][graph*2+head]
static __device__ float  g_adst[N_NODES * 4];
static __device__ int    g_deg [NSEG];           // in-degree (incl self loop)
static __device__ int    g_off [NSEG + 1];       // CSR offsets
static __device__ int    g_cur [NSEG];           // placement cursors
static __device__ int    g_csr [2 * EN_TOT];     // src ids sorted by (graph,dst)

#define FFMA2(d, a, b) asm("fma.rn.f32x2 %0, %1, %2, %0;" : "+l"(d) : "l"(a), "l"(b))

__device__ __forceinline__ float f2lo(ull v) { return __uint_as_float((unsigned)v); }
__device__ __forceinline__ float f2hi(ull v) { return __uint_as_float((unsigned)(v >> 32)); }
__device__ __forceinline__ ull packf2(float lo, float hi) {
    return ((ull)__float_as_uint(hi) << 32) | (ull)__float_as_uint(lo);
}

// ---------------- deg init (self loop counts as 1) ----------------
__global__ void k_zero() {
    int i = blockIdx.x * blockDim.x + threadIdx.x;
    if (i < NSEG) g_deg[i] = 1;
}

// ---------------- GEMM 128x128 tiles, FFMA2, fused attention dots ----------------
__global__ void __launch_bounds__(256) k_gemm(
    const float* __restrict__ x,
    const float* __restrict__ W1, const float* __restrict__ W2,
    const float* __restrict__ as1, const float* __restrict__ ad1,
    const float* __restrict__ as2, const float* __restrict__ ad2)
{
    __shared__ float As [16][128];   // x tile, [k][row]
    __shared__ float Bs2[16][256];   // W tile, value-duplicated along cols
    __shared__ float satt_s[128], satt_d[128];

    const int g  = blockIdx.y;
    const float* W = g ? W2 : W1;
    const int n0 = blockIdx.x * 128;
    const int t  = threadIdx.x;
    const int tx = t & 15, ty = t >> 4;

    if (t < 128) {
        satt_s[t] = (g ? as2 : as1)[t];
        satt_d[t] = (g ? ad2 : ad1)[t];
    }

    ull acc2[4][8];
#pragma unroll
    for (int i = 0; i < 4; i++)
#pragma unroll
        for (int j = 0; j < 8; j++) acc2[i][j] = 0ull;

    for (int k0 = 0; k0 < 256; k0 += 16) {
        // load X tile (transpose to [k][row])
#pragma unroll
        for (int i = 0; i < 2; i++) {
            int f = t + i * 256;
            int row = f >> 2, c4 = (f & 3) * 4;
            float4 v = make_float4(0.f, 0.f, 0.f, 0.f);
            if (n0 + row < N_NODES)
                v = *(const float4*)(x + (size_t)(n0 + row) * 256 + k0 + c4);
            As[c4 + 0][row] = v.x;
            As[c4 + 1][row] = v.y;
            As[c4 + 2][row] = v.z;
            As[c4 + 3][row] = v.w;
        }
        // load W tile duplicated: Bs2[kk][2c]=Bs2[kk][2c+1]=W[kk][c]
#pragma unroll
        for (int i = 0; i < 2; i++) {
            int f = t + i * 256;
            int kk = f >> 5, c4 = (f & 31) * 4;
            float4 v = *(const float4*)(W + (size_t)(k0 + kk) * 128 + c4);
            *(float4*)&Bs2[kk][2 * c4]     = make_float4(v.x, v.x, v.y, v.y);
            *(float4*)&Bs2[kk][2 * c4 + 4] = make_float4(v.z, v.z, v.w, v.w);
        }
        __syncthreads();

#pragma unroll
        for (int kk = 0; kk < 16; kk++) {
            ulonglong2 a01 = *(const ulonglong2*)&As[kk][ty * 8];
            ulonglong2 a23 = *(const ulonglong2*)&As[kk][ty * 8 + 4];
            ull aa[4] = {a01.x, a01.y, a23.x, a23.y};
            ull bb[8];
#pragma unroll
            for (int jj = 0; jj < 8; jj++)
                bb[jj] = *(const ull*)&Bs2[kk][(tx + 16 * jj) * 2];
#pragma unroll
            for (int i2 = 0; i2 < 4; i2++)
#pragma unroll
                for (int jj = 0; jj < 8; jj++)
                    FFMA2(acc2[i2][jj], aa[i2], bb[jj]);
        }
        __syncthreads();
    }

    // epilogue: store h + per-row attention dot products
    float* hbase = (float*)g_h4;
#pragma unroll
    for (int i2 = 0; i2 < 4; i2++) {
#pragma unroll
        for (int half = 0; half < 2; half++) {
            int row = n0 + ty * 8 + 2 * i2 + half;
            bool ok = row < N_NODES;
            float vv[8];
#pragma unroll
            for (int jj = 0; jj < 8; jj++)
                vv[jj] = half ? f2hi(acc2[i2][jj]) : f2lo(acc2[i2][jj]);
            float ds0 = 0.f, ds1 = 0.f, dd0 = 0.f, dd1 = 0.f;
#pragma unroll
            for (int jj = 0; jj < 8; jj++) {
                int col = tx + 16 * jj;
                if (ok) hbase[(size_t)row * 256 + g * 128 + col] = vv[jj];
                int ai = ((jj >> 2) << 6) + tx + (jj & 3) * 16;  // head*64 + (col&63)
                if (jj < 4) { ds0 = fmaf(vv[jj], satt_s[ai], ds0); dd0 = fmaf(vv[jj], satt_d[ai], dd0); }
                else        { ds1 = fmaf(vv[jj], satt_s[ai], ds1); dd1 = fmaf(vv[jj], satt_d[ai], dd1); }
            }
#pragma unroll
            for (int off = 8; off; off >>= 1) {
                ds0 += __shfl_down_sync(0xffffffffu, ds0, off, 16);
                ds1 += __shfl_down_sync(0xffffffffu, ds1, off, 16);
                dd0 += __shfl_down_sync(0xffffffffu, dd0, off, 16);
                dd1 += __shfl_down_sync(0xffffffffu, dd1, off, 16);
            }
            if (tx == 0 && ok) {
                int b = row * 4 + g * 2;
                g_asrc[b]     = ds0;
                g_asrc[b + 1] = ds1;
                g_adst[b]     = dd0;
                g_adst[b + 1] = dd1;
            }
        }
    }
}

// ---------------- degree histogram ----------------
__global__ void k_deg(const int* __restrict__ eic, const int* __restrict__ eil) {
    int i = blockIdx.x * blockDim.x + threadIdx.x;
    if (i >= E_EDGES) return;
    int g = blockIdx.y;
    const int* ei = g ? eil : eic;
    atomicAdd(&g_deg[g * N_NODES + ei[E_EDGES + i]], 1);
}

// ---------------- single-block exclusive scan over 2N degrees ----------------
__global__ void k_scan() {
    __shared__ int part[1024];
    const int t = threadIdx.x;
    const int n = NSEG;
    const int chunk = (n + 1023) / 1024;
    int begin = t * chunk;
    int stop  = begin + chunk; if (stop > n) stop = n;
    int s = 0;
    for (int i = begin; i < stop; i++) s += g_deg[i];
    part[t] = s;
    __syncthreads();
    for (int off = 1; off < 1024; off <<= 1) {
        int v = (t >= off) ? part[t - off] : 0;
        __syncthreads();
        part[t] += v;
        __syncthreads();
    }
    int run = (t == 0) ? 0 : part[t - 1];
    for (int i = begin; i < stop; i++) {
        g_off[i] = run;
        g_cur[i] = run;
        run += g_deg[i];
    }
    if (t == 1023) g_off[n] = run;
}

// ---------------- CSR placement (edges + self loops) ----------------
__global__ void k_place(const int* __restrict__ eic, const int* __restrict__ eil) {
    int i = blockIdx.x * blockDim.x + threadIdx.x;
    if (i >= EN_TOT) return;
    int g = blockIdx.y;
    const int* ei = g ? eil : eic;
    int src, dst;
    if (i < E_EDGES) { src = ei[i]; dst = ei[E_EDGES + i]; }
    else             { src = dst = i - E_EDGES; }
    int pos = atomicAdd(&g_cur[g * N_NODES + dst], 1);
    g_csr[pos] = src;
}

// ---------------- gather: softmax (no max-sub) + aggregate + bias + relu ----------------
__global__ void __launch_bounds__(256) k_gather(
    const float* __restrict__ b1, const float* __restrict__ b2)
{
    int w = blockIdx.x * 8 + (threadIdx.x >> 5);
    int node = w >> 1, g = w & 1;
    if (node >= N_NODES) return;
    int lane = threadIdx.x & 31;
    int head = lane >> 4;

    int seg = g * N_NODES + node;
    int e   = g_off[seg];
    int end = g_off[seg + 1];
    float ad = g_adst[node * 4 + g * 2 + head];

    float4 acc = make_float4(0.f, 0.f, 0.f, 0.f);
    float ssum = 0.f;
    int src = g_csr[e];
    for (; e < end; e++) {
        int nsrc = (e + 1 < end) ? g_csr[e + 1] : 0;
        float as = g_asrc[src * 4 + g * 2 + head];
        float4 hv = g_h4[(size_t)src * 64 + g * 32 + lane];
        float ee = as + ad;
        ee = ee >= 0.f ? ee : 0.2f * ee;
        float p = __expf(ee);
        ssum += p;
        acc.x = fmaf(p, hv.x, acc.x);
        acc.y = fmaf(p, hv.y, acc.y);
        acc.z = fmaf(p, hv.z, acc.z);
        acc.w = fmaf(p, hv.w, acc.w);
        src = nsrc;
    }
    float r = 1.f / ssum;
    const float* bias = g ? b2 : b1;
    float4 bv = *(const float4*)(bias + lane * 4);
    float4 o;
    o.x = fmaxf(fmaf(acc.x, r, bv.x), 0.f);
    o.y = fmaxf(fmaf(acc.y, r, bv.y), 0.f);
    o.z = fmaxf(fmaf(acc.z, r, bv.z), 0.f);
    o.w = fmaxf(fmaf(acc.w, r, bv.w), 0.f);
    g_acc4[(size_t)node * 64 + g * 32 + lane] = o;
}

// ---------------- FC (concat already materialized), FFMA2 ----------------
__global__ void __launch_bounds__(256) k_fc(
    const float* __restrict__ fcW, const float* __restrict__ fcb,
    float* __restrict__ out)
{
    __shared__ float s2[16][512];   // duplicated activations
    const int n0 = blockIdx.x * 16;
    const int t  = threadIdx.x;
    const float* acc = (const float*)g_acc4;
#pragma unroll
    for (int i = 0; i < 16; i++) {
        float v = acc[(size_t)(n0 + i) * 256 + t];
        s2[i][2 * t]     = v;
        s2[i][2 * t + 1] = v;
    }
    __syncthreads();

    const int node = t >> 4;
    const int o4   = (t & 15) * 4;
    float4 bb = *(const float4*)(fcb + o4);
    ull a0 = packf2(bb.x, bb.y);
    ull a1 = packf2(bb.z, bb.w);
    const float* wp = fcW + o4;
#pragma unroll 8
    for (int k = 0; k < 256; k++) {
        ull sv = *(const ull*)&s2[node][2 * k];
        ulonglong2 wv = *(const ulonglong2*)(wp + (size_t)k * 64);
        FFMA2(a0, sv, wv.x);
        FFMA2(a1, sv, wv.y);
    }
    float4 o = make_float4(f2lo(a0), f2hi(a0), f2lo(a1), f2hi(a1));
    *(float4*)(out + (size_t)(n0 + node) * 64 + o4) = o;
}

// ---------------- launcher ----------------
extern "C" void kernel_launch(void* const* d_in, const int* in_sizes, int n_in,
                              void* d_out, int out_size) {
    const float* x   = (const float*)d_in[0];
    const int*   eic = (const int*)d_in[1];
    const int*   eil = (const int*)d_in[2];
    const float* W1  = (const float*)d_in[3];
    const float* as1 = (const float*)d_in[4];
    const float* ad1 = (const float*)d_in[5];
    const float* b1  = (const float*)d_in[6];
    const float* W2  = (const float*)d_in[7];
    const float* as2 = (const float*)d_in[8];
    const float* ad2 = (const float*)d_in[9];
    const float* b2  = (const float*)d_in[10];
    const float* fcW = (const float*)d_in[11];
    const float* fcb = (const float*)d_in[12];
    float* out = (float*)d_out;

    k_zero<<<(NSEG + 255) / 256, 256>>>();

    dim3 gg((N_NODES + 127) / 128, 2);
    k_gemm<<<gg, 256>>>(x, W1, W2, as1, ad1, as2, ad2);

    dim3 gd((E_EDGES + 255) / 256, 2);
    k_deg<<<gd, 256>>>(eic, eil);

    k_scan<<<1, 1024>>>();

    dim3 gp((EN_TOT + 255) / 256, 2);
    k_place<<<gp, 256>>>(eic, eil);

    k_gather<<<(2 * N_NODES + 7) / 8, 256>>>(b1, b2);

    k_fc<<<N_NODES / 16, 256>>>(fcW, fcb, out);
}